// round 12
// baseline (speedup 1.0000x reference)
#include <cuda_runtime.h>
#include <math.h>

// Shape (2,3,128,128,128) fp32
#define NTOT   12582912
#define NGRP   49152          // 6*128*64 groups of 2 consecutive y-rows
#define ALPHA  0.001
#define WPB    4
#define BLOCK  (WPB * 32)
#define GRID   (NGRP / WPB)   // 12288

__device__ double       g_acc[3];
__device__ unsigned int g_ticket;

__device__ __forceinline__ float4 f4sub(float4 a, float4 b) {
    return make_float4(a.x - b.x, a.y - b.y, a.z - b.z, a.w - b.w);
}
__device__ __forceinline__ float4 f4add(float4 a, float4 b) {
    return make_float4(a.x + b.x, a.y + b.y, a.z + b.z, a.w + b.w);
}

// One warp per group of 2 consecutive y-rows (fixed vol,z); lane = float4 of x.
// Only 4 y-levels of state -> low registers -> high occupancy.
__global__ __launch_bounds__(BLOCK) void ace_main(
    const float* __restrict__ yp, const float* __restrict__ yt,
    float* __restrict__ out)
{
    const unsigned FULL = 0xFFFFFFFFu;
    const int wid  = threadIdx.x >> 5;
    const int lane = threadIdx.x & 31;
    const int g    = blockIdx.x * WPB + wid;

    const int y0  = (g & 63) << 1;          // first of 2 output rows
    const int z   = (g >> 6) & 127;
    const int vol = g >> 13;
    const int zm_ = z > 0   ? z - 1 : 0;
    const int zq  = z < 127 ? z + 1 : 127;

    const float* U = yp + ((size_t)vol << 21);
    const float* T = yt + ((size_t)vol << 21);

    // level l corresponds to y = clamp(y0-1+l), l = 0..3
    float4 cz[4], ez[4], sz[4];
    float4 tv[2];

    #define LOADLVL(l)                                                          \
    {   int yy = y0 - 1 + (l);                                                  \
        yy = yy < 0 ? 0 : (yy > 127 ? 127 : yy);                                \
        const float4 a_ = __ldg(((const float4*)(U + ((zm_ << 14) + (yy << 7)))) + lane); \
        const float4 b_ = __ldg(((const float4*)(U + ((zq  << 14) + (yy << 7)))) + lane); \
        const float4 c_ = __ldg(((const float4*)(U + ((z   << 14) + (yy << 7)))) + lane); \
        cz[l] = c_; ez[l] = f4sub(b_, a_); sz[l] = f4add(b_, a_);               \
    }
    #define LOADT(j)                                                            \
        tv[j] = __ldg(((const float4*)(T + ((z << 14) + ((y0 + (j)) << 7)))) + lane);

    LOADLVL(0) LOADLVL(1) LOADLVL(2)
    LOADT(0)

    // 6-wide clamped x-window from a float4
    #define MK6(A, V)                                                  \
        float A[6];                                                    \
        A[1] = V.x; A[2] = V.y; A[3] = V.z; A[4] = V.w;                \
        {   float L_ = __shfl_up_sync(FULL, A[4], 1);                  \
            float R_ = __shfl_down_sync(FULL, A[1], 1);                \
            A[0] = (lane == 0)  ? A[1] : L_;                           \
            A[5] = (lane == 31) ? A[4] : R_; }

    float ain = 0.f, aout = 0.f, ael = 0.f;

    #pragma unroll
    for (int j = 0; j < 2; j++) {
        if (j < 1) { LOADLVL(3) LOADT(1) }          // prefetch remaining

        const int l = j + 1;
        const float4 eyv  = f4sub(cz[l + 1], cz[l - 1]);   // u(y+1)-u(y-1)
        const float4 syv  = f4add(cz[l + 1], cz[l - 1]);
        const float4 gxyv = f4sub(ez[l + 1], ez[l - 1]);   // mixed z,y
        const float4 szl  = sz[l];

        MK6(cc,  cz[l])
        MK6(ezw, ez[l])
        MK6(eyw, eyv)

        const float syA [4] = { syv.x,  syv.y,  syv.z,  syv.w  };
        const float szA [4] = { szl.x,  szl.y,  szl.z,  szl.w  };
        const float gxyA[4] = { gxyv.x, gxyv.y, gxyv.z, gxyv.w };
        const float ttA [4] = { tv[j].x, tv[j].y, tv[j].z, tv[j].w };

        #pragma unroll
        for (int k = 0; k < 4; k++) {
            const float uc = cc[k + 1];
            const float di = ezw[k + 1];
            const float dj = eyw[k + 1];
            const float dk = cc[k + 2] - cc[k];

            const float cii = fmaf(uc, -2.f, szA[k]);
            const float cjj = fmaf(uc, -2.f, syA[k]);
            const float ckk = fmaf(uc, -2.f, cc[k] + cc[k + 2]);
            const float lap = cii + cjj + ckk;

            const float Dik = ezw[k + 2] - ezw[k];
            const float Djk = eyw[k + 2] - eyw[k];
            const float Dij = gxyA[k];

            const float di2 = di * di, dj2 = dj * dj, dk2 = dk * dk;
            const float S = di2 + dj2 + dk2;             // = 4*(ci2+cj2+ck2)

            float acc = di2 * cii;
            acc = fmaf(dj2, cjj, acc);
            acc = fmaf(dk2, ckk, acc);
            acc = fmaf(Dik * Djk, Dij, acc);
            const float curv = fmaf(0.25f, fmaf(S, lap, -acc), lap);

            const float ee = fmaf(0.25f, S, 1e-8f);      // eps + s
            const float oo = fmaf(0.25f, S, 1.f);        // (sqrt(1+s)+eps)^2 ~ 1+s
            // sqrt(ee)/oo == ee * rsqrt(ee*oo^2)  (one MUFU.RSQ, no div/sqrt)
            const float r_ = rsqrtf(ee * oo * oo);
            ael = fmaf(curv * curv * ee, r_, ael);

            const float t = ttA[k];
            const float tm1 = t - 1.f;
            ain  = fmaf(uc, tm1 * tm1, ain);
            aout = fmaf(1.f - uc, t * t, aout);
        }
    }
    #undef MK6
    #undef LOADLVL
    #undef LOADT

    // ---- block reduction ----
    #pragma unroll
    for (int o = 16; o > 0; o >>= 1) {
        ain  += __shfl_down_sync(FULL, ain,  o);
        aout += __shfl_down_sync(FULL, aout, o);
        ael  += __shfl_down_sync(FULL, ael,  o);
    }
    __shared__ float si[WPB], so[WPB], se[WPB];
    if (lane == 0) { si[wid] = ain; so[wid] = aout; se[wid] = ael; }
    __syncthreads();

    if (threadIdx.x == 0) {
        float A = si[0] + si[1] + si[2] + si[3];
        float B = so[0] + so[1] + so[2] + so[3];
        float E = se[0] + se[1] + se[2] + se[3];
        atomicAdd(&g_acc[0], (double)A);
        atomicAdd(&g_acc[1], (double)B);
        atomicAdd(&g_acc[2], (double)E);
        __threadfence();
        unsigned t = atomicAdd(&g_ticket, 1u);
        if (t == (unsigned)(GRID - 1)) {          // last block finalizes + resets
            __threadfence();
            double s0 = atomicAdd(&g_acc[0], 0.0);
            double s1 = atomicAdd(&g_acc[1], 0.0);
            double s2 = atomicAdd(&g_acc[2], 0.0);
            double res = fabs(s0) + fabs(s1) + s2 + ALPHA * (double)NTOT;
            out[0] = (float)res;
            g_acc[0] = 0.0; g_acc[1] = 0.0; g_acc[2] = 0.0;
            g_ticket = 0u;
        }
    }
}

extern "C" void kernel_launch(void* const* d_in, const int* in_sizes, int n_in,
                              void* d_out, int out_size) {
    const float* y_pred = (const float*)d_in[0];
    const float* y_true = (const float*)d_in[1];
    ace_main<<<GRID, BLOCK>>>(y_pred, y_true, (float*)d_out);
}

// round 13
// speedup vs baseline: 1.2363x; 1.2363x over previous
#include <cuda_runtime.h>
#include <math.h>

// Shape (2,3,128,128,128) fp32
#define NTOT   12582912
#define ALPHA  0.001
#define WPB    4
#define BLOCK  (WPB * 32)
#define GRID   6144           // 6 vol * 32 z-blocks * 32 y-groups

__device__ double       g_acc[3];
__device__ unsigned int g_ticket;

__device__ __forceinline__ float4 f4sub(float4 a, float4 b) {
    return make_float4(a.x - b.x, a.y - b.y, a.z - b.z, a.w - b.w);
}
__device__ __forceinline__ float4 f4add(float4 a, float4 b) {
    return make_float4(a.x + b.x, a.y + b.y, a.z + b.z, a.w + b.w);
}

// Block = 4 warps at 4 CONSECUTIVE z (same 4-row y-group): sibling warps share
// 2/3 of their z-planes -> those LDGs hit L1 instead of L2.
// Each warp: 4 consecutive y-rows at its z; lane = float4 of x.
__global__ __launch_bounds__(BLOCK, 6) void ace_main(
    const float* __restrict__ yp, const float* __restrict__ yt,
    float* __restrict__ out)
{
    const unsigned FULL = 0xFFFFFFFFu;
    const int wid  = threadIdx.x >> 5;
    const int lane = threadIdx.x & 31;
    const int g    = blockIdx.x;

    const int y0  = (g & 31) << 2;            // first of 4 output rows
    const int z   = (((g >> 5) & 31) << 2) + wid;  // this warp's z
    const int vol = g >> 10;
    const int zm_ = z > 0   ? z - 1 : 0;
    const int zq  = z < 127 ? z + 1 : 127;

    const float* U = yp + ((size_t)vol << 21);
    const float* T = yt + ((size_t)vol << 21);

    // level l corresponds to y = clamp(y0-1+l), l = 0..5
    float4 cz[6], ez[6], sz[6];
    float4 tv[4];

    #define LOADLVL(l)                                                          \
    {   int yy = y0 - 1 + (l);                                                  \
        yy = yy < 0 ? 0 : (yy > 127 ? 127 : yy);                                \
        const float4 a_ = __ldg(((const float4*)(U + ((zm_ << 14) + (yy << 7)))) + lane); \
        const float4 b_ = __ldg(((const float4*)(U + ((zq  << 14) + (yy << 7)))) + lane); \
        const float4 c_ = __ldg(((const float4*)(U + ((z   << 14) + (yy << 7)))) + lane); \
        cz[l] = c_; ez[l] = f4sub(b_, a_); sz[l] = f4add(b_, a_);               \
    }
    #define LOADT(j)                                                            \
        tv[j] = __ldg(((const float4*)(T + ((z << 14) + ((y0 + (j)) << 7)))) + lane);

    LOADLVL(0) LOADLVL(1) LOADLVL(2) LOADLVL(3)
    LOADT(0)

    // 6-wide clamped x-window from a float4
    #define MK6(A, V)                                                  \
        float A[6];                                                    \
        A[1] = V.x; A[2] = V.y; A[3] = V.z; A[4] = V.w;                \
        {   float L_ = __shfl_up_sync(FULL, A[4], 1);                  \
            float R_ = __shfl_down_sync(FULL, A[1], 1);                \
            A[0] = (lane == 0)  ? A[1] : L_;                           \
            A[5] = (lane == 31) ? A[4] : R_; }

    float ain = 0.f, aout = 0.f, ael = 0.f;

    #pragma unroll
    for (int j = 0; j < 4; j++) {
        if (j < 2) LOADLVL(j + 4)                  // prefetch remaining levels
        if (j < 3) LOADT(j + 1)                    // t prefetch, distance 1

        const int l = j + 1;
        const float4 eyv  = f4sub(cz[l + 1], cz[l - 1]);   // u(y+1)-u(y-1)
        const float4 syv  = f4add(cz[l + 1], cz[l - 1]);
        const float4 gxyv = f4sub(ez[l + 1], ez[l - 1]);   // mixed z,y
        const float4 szl  = sz[l];

        MK6(cc,  cz[l])
        MK6(ezw, ez[l])
        MK6(eyw, eyv)

        const float syA [4] = { syv.x,  syv.y,  syv.z,  syv.w  };
        const float szA [4] = { szl.x,  szl.y,  szl.z,  szl.w  };
        const float gxyA[4] = { gxyv.x, gxyv.y, gxyv.z, gxyv.w };
        const float ttA [4] = { tv[j].x, tv[j].y, tv[j].z, tv[j].w };

        #pragma unroll
        for (int k = 0; k < 4; k++) {
            const float uc = cc[k + 1];
            const float di = ezw[k + 1];
            const float dj = eyw[k + 1];
            const float dk = cc[k + 2] - cc[k];

            const float cii = fmaf(uc, -2.f, szA[k]);
            const float cjj = fmaf(uc, -2.f, syA[k]);
            const float ckk = fmaf(uc, -2.f, cc[k] + cc[k + 2]);
            const float lap = cii + cjj + ckk;

            const float Dik = ezw[k + 2] - ezw[k];
            const float Djk = eyw[k + 2] - eyw[k];
            const float Dij = gxyA[k];

            const float di2 = di * di, dj2 = dj * dj, dk2 = dk * dk;
            const float S = di2 + dj2 + dk2;             // = 4*(ci2+cj2+ck2)

            float acc = di2 * cii;
            acc = fmaf(dj2, cjj, acc);
            acc = fmaf(dk2, ckk, acc);
            acc = fmaf(Dik * Djk, Dij, acc);
            const float curv = fmaf(0.25f, fmaf(S, lap, -acc), lap);

            const float ee = fmaf(0.25f, S, 1e-8f);      // eps + s
            const float oo = fmaf(0.25f, S, 1.f);        // (sqrt(1+s)+eps)^2 ~ 1+s
            // sqrt(ee)/oo == ee * rsqrt(ee*oo^2)
            const float r_ = rsqrtf(ee * oo * oo);
            ael = fmaf(curv * curv * ee, r_, ael);

            const float t = ttA[k];
            const float tm1 = t - 1.f;
            ain  = fmaf(uc, tm1 * tm1, ain);
            aout = fmaf(1.f - uc, t * t, aout);
        }
    }
    #undef MK6
    #undef LOADLVL
    #undef LOADT

    // ---- block reduction ----
    #pragma unroll
    for (int o = 16; o > 0; o >>= 1) {
        ain  += __shfl_down_sync(FULL, ain,  o);
        aout += __shfl_down_sync(FULL, aout, o);
        ael  += __shfl_down_sync(FULL, ael,  o);
    }
    __shared__ float si[WPB], so[WPB], se[WPB];
    if (lane == 0) { si[wid] = ain; so[wid] = aout; se[wid] = ael; }
    __syncthreads();

    if (threadIdx.x == 0) {
        float A = si[0] + si[1] + si[2] + si[3];
        float B = so[0] + so[1] + so[2] + so[3];
        float E = se[0] + se[1] + se[2] + se[3];
        atomicAdd(&g_acc[0], (double)A);
        atomicAdd(&g_acc[1], (double)B);
        atomicAdd(&g_acc[2], (double)E);
        __threadfence();
        unsigned t = atomicAdd(&g_ticket, 1u);
        if (t == (unsigned)(GRID - 1)) {          // last block finalizes + resets
            __threadfence();
            double s0 = atomicAdd(&g_acc[0], 0.0);
            double s1 = atomicAdd(&g_acc[1], 0.0);
            double s2 = atomicAdd(&g_acc[2], 0.0);
            double res = fabs(s0) + fabs(s1) + s2 + ALPHA * (double)NTOT;
            out[0] = (float)res;
            g_acc[0] = 0.0; g_acc[1] = 0.0; g_acc[2] = 0.0;
            g_ticket = 0u;
        }
    }
}

extern "C" void kernel_launch(void* const* d_in, const int* in_sizes, int n_in,
                              void* d_out, int out_size) {
    const float* y_pred = (const float*)d_in[0];
    const float* y_true = (const float*)d_in[1];
    ace_main<<<GRID, BLOCK>>>(y_pred, y_true, (float*)d_out);
}

// round 14
// speedup vs baseline: 1.2886x; 1.0423x over previous
#include <cuda_runtime.h>
#include <math.h>

// Shape (2,3,128,128,128) fp32
#define NTOT   12582912
#define NGRP   24576          // 6*128*32 groups of 4 consecutive y-rows
#define ALPHA  0.001
#define WPB    4
#define BLOCK  (WPB * 32)
#define GRID   (NGRP / WPB)   // 6144

// g_acc: [0]=A=Σu·t², [1]=B=Σu·t, [2]=C=Σu, [3]=D=Σt², [4]=E=elastica curv part
__device__ double       g_acc[5];
__device__ unsigned int g_ticket;

__device__ __forceinline__ float4 f4sub(float4 a, float4 b) {
    return make_float4(a.x - b.x, a.y - b.y, a.z - b.z, a.w - b.w);
}
__device__ __forceinline__ float4 f4add(float4 a, float4 b) {
    return make_float4(a.x + b.x, a.y + b.y, a.z + b.z, a.w + b.w);
}

// One warp per group of 4 consecutive y-rows (fixed vol,z); lane = float4 of x.
__global__ __launch_bounds__(BLOCK, 6) void ace_main(
    const float* __restrict__ yp, const float* __restrict__ yt,
    float* __restrict__ out)
{
    const unsigned FULL = 0xFFFFFFFFu;
    const int wid  = threadIdx.x >> 5;
    const int lane = threadIdx.x & 31;
    const int g    = blockIdx.x * WPB + wid;

    const int y0  = (g & 31) << 2;          // first of 4 output rows
    const int z   = (g >> 5) & 127;
    const int vol = g >> 12;
    const int zm_ = z > 0   ? z - 1 : 0;
    const int zq  = z < 127 ? z + 1 : 127;

    const float* U = yp + ((size_t)vol << 21);
    const float* T = yt + ((size_t)vol << 21);

    // level l corresponds to y = clamp(y0-1+l), l = 0..5
    float4 cz[6], ez[6], sz[6];
    float4 tv[4];

    #define LOADLVL(l)                                                          \
    {   int yy = y0 - 1 + (l);                                                  \
        yy = yy < 0 ? 0 : (yy > 127 ? 127 : yy);                                \
        const float4 a_ = __ldg(((const float4*)(U + ((zm_ << 14) + (yy << 7)))) + lane); \
        const float4 b_ = __ldg(((const float4*)(U + ((zq  << 14) + (yy << 7)))) + lane); \
        const float4 c_ = __ldg(((const float4*)(U + ((z   << 14) + (yy << 7)))) + lane); \
        cz[l] = c_; ez[l] = f4sub(b_, a_); sz[l] = f4add(b_, a_);               \
    }
    #define LOADT(j)                                                            \
        tv[j] = __ldg(((const float4*)(T + ((z << 14) + ((y0 + (j)) << 7)))) + lane);

    LOADLVL(0) LOADLVL(1) LOADLVL(2) LOADLVL(3)
    LOADT(0)

    // 6-wide clamped x-window from a float4
    #define MK6(A, V)                                                  \
        float A[6];                                                    \
        A[1] = V.x; A[2] = V.y; A[3] = V.z; A[4] = V.w;                \
        {   float L_ = __shfl_up_sync(FULL, A[4], 1);                  \
            float R_ = __shfl_down_sync(FULL, A[1], 1);                \
            A[0] = (lane == 0)  ? A[1] : L_;                           \
            A[5] = (lane == 31) ? A[4] : R_; }

    float aA = 0.f, aB = 0.f, aC = 0.f, aD = 0.f, ael = 0.f;

    #pragma unroll
    for (int j = 0; j < 4; j++) {
        if (j < 2) LOADLVL(j + 4)                  // prefetch remaining levels
        if (j < 3) LOADT(j + 1)                    // t prefetch, distance 1

        const int l = j + 1;
        const float4 eyv  = f4sub(cz[l + 1], cz[l - 1]);   // u(y+1)-u(y-1)
        const float4 syv  = f4add(cz[l + 1], cz[l - 1]);
        const float4 gxyv = f4sub(ez[l + 1], ez[l - 1]);   // mixed z,y
        const float4 szl  = sz[l];

        MK6(cc,  cz[l])
        MK6(ezw, ez[l])
        MK6(eyw, eyv)

        const float syA [4] = { syv.x,  syv.y,  syv.z,  syv.w  };
        const float szA [4] = { szl.x,  szl.y,  szl.z,  szl.w  };
        const float gxyA[4] = { gxyv.x, gxyv.y, gxyv.z, gxyv.w };
        const float ttA [4] = { tv[j].x, tv[j].y, tv[j].z, tv[j].w };

        #pragma unroll
        for (int k = 0; k < 4; k++) {
            const float uc = cc[k + 1];
            const float di = ezw[k + 1];
            const float dj = eyw[k + 1];
            const float dk = cc[k + 2] - cc[k];

            const float cii = fmaf(uc, -2.f, szA[k]);
            const float cjj = fmaf(uc, -2.f, syA[k]);
            const float ckk = fmaf(uc, -2.f, cc[k] + cc[k + 2]);
            const float lap = cii + cjj + ckk;

            const float Dik = ezw[k + 2] - ezw[k];
            const float Djk = eyw[k + 2] - eyw[k];
            const float Dij = gxyA[k];

            const float di2 = di * di, dj2 = dj * dj, dk2 = dk * dk;
            const float S = di2 + dj2 + dk2;             // = 4*(ci2+cj2+ck2)

            float acc = di2 * cii;
            acc = fmaf(dj2, cjj, acc);
            acc = fmaf(dk2, ckk, acc);
            acc = fmaf(Dik * Djk, Dij, acc);
            const float curv = fmaf(0.25f, fmaf(S, lap, -acc), lap);

            const float ee = fmaf(0.25f, S, 1e-8f);      // eps + s
            const float oo = fmaf(0.25f, S, 1.f);        // (sqrt(1+s)+eps)^2 ~ 1+s
            // sqrt(ee)/oo == ee * rsqrt(ee*oo^2)
            const float r_ = rsqrtf(ee * oo * oo);
            ael = fmaf(curv * curv * ee, r_, ael);

            // region moments: A=Σu·t², B=Σu·t, C=Σu, D=Σt²
            const float t  = ttA[k];
            const float t2 = t * t;
            aA = fmaf(uc, t2, aA);
            aB = fmaf(uc, t,  aB);
            aC += uc;
            aD += t2;
        }
    }
    #undef MK6
    #undef LOADLVL
    #undef LOADT

    // ---- block reduction (5 accumulators) ----
    #pragma unroll
    for (int o = 16; o > 0; o >>= 1) {
        aA  += __shfl_down_sync(FULL, aA,  o);
        aB  += __shfl_down_sync(FULL, aB,  o);
        aC  += __shfl_down_sync(FULL, aC,  o);
        aD  += __shfl_down_sync(FULL, aD,  o);
        ael += __shfl_down_sync(FULL, ael, o);
    }
    __shared__ float sA[WPB], sB[WPB], sC[WPB], sD[WPB], sE[WPB];
    if (lane == 0) { sA[wid] = aA; sB[wid] = aB; sC[wid] = aC; sD[wid] = aD; sE[wid] = ael; }
    __syncthreads();

    if (threadIdx.x == 0) {
        atomicAdd(&g_acc[0], (double)(sA[0] + sA[1] + sA[2] + sA[3]));
        atomicAdd(&g_acc[1], (double)(sB[0] + sB[1] + sB[2] + sB[3]));
        atomicAdd(&g_acc[2], (double)(sC[0] + sC[1] + sC[2] + sC[3]));
        atomicAdd(&g_acc[3], (double)(sD[0] + sD[1] + sD[2] + sD[3]));
        atomicAdd(&g_acc[4], (double)(sE[0] + sE[1] + sE[2] + sE[3]));
        __threadfence();
        unsigned t = atomicAdd(&g_ticket, 1u);
        if (t == (unsigned)(GRID - 1)) {          // last block finalizes + resets
            __threadfence();
            double A = atomicAdd(&g_acc[0], 0.0);
            double B = atomicAdd(&g_acc[1], 0.0);
            double C = atomicAdd(&g_acc[2], 0.0);
            double D = atomicAdd(&g_acc[3], 0.0);
            double E = atomicAdd(&g_acc[4], 0.0);
            const double region_in  = A - 2.0 * B + C;   // Σ u (t-1)^2
            const double region_out = D - A;             // Σ (1-u) t^2
            double res = fabs(region_in) + fabs(region_out) + E + ALPHA * (double)NTOT;
            out[0] = (float)res;
            g_acc[0] = 0.0; g_acc[1] = 0.0; g_acc[2] = 0.0; g_acc[3] = 0.0; g_acc[4] = 0.0;
            g_ticket = 0u;
        }
    }
}

extern "C" void kernel_launch(void* const* d_in, const int* in_sizes, int n_in,
                              void* d_out, int out_size) {
    const float* y_pred = (const float*)d_in[0];
    const float* y_true = (const float*)d_in[1];
    ace_main<<<GRID, BLOCK>>>(y_pred, y_true, (float*)d_out);
}

// round 15
// speedup vs baseline: 1.7409x; 1.3510x over previous
#include <cuda_runtime.h>
#include <math.h>

// Shape (2,3,128,128,128) fp32
#define NTOT   12582912
#define ALPHA  0.001
#define WPB    4
#define BLOCK  (WPB * 32)
#define NWRP   6144           // 6 vol * 16 z-tiles * 64 y-groups
#define GRID   (NWRP / WPB)   // 1536

__device__ double       g_acc[3];
__device__ unsigned int g_ticket;

__device__ __forceinline__ float4 f4sub(float4 a, float4 b) {
    return make_float4(a.x - b.x, a.y - b.y, a.z - b.z, a.w - b.w);
}
__device__ __forceinline__ float4 f4add(float4 a, float4 b) {
    return make_float4(a.x + b.x, a.y + b.y, a.z + b.z, a.w + b.w);
}

// One warp: 2 consecutive y-rows x 8 consecutive z (z-sliding ring of 3 raw
// planes per y-level). lane = float4 of x.
__global__ __launch_bounds__(BLOCK) void ace_main(
    const float* __restrict__ yp, const float* __restrict__ yt,
    float* __restrict__ out)
{
    const unsigned FULL = 0xFFFFFFFFu;
    const int wid  = threadIdx.x >> 5;
    const int lane = threadIdx.x & 31;
    const int g    = blockIdx.x * WPB + wid;

    const int y0  = (g & 63) << 1;           // 2 output rows: y0, y0+1
    const int z0  = ((g >> 6) & 15) << 3;    // 8 output z: z0..z0+7
    const int vol = g >> 10;

    const float* U = yp + ((size_t)vol << 21);
    const float* T = yt + ((size_t)vol << 21);

    // y-level offsets (clamped), l=0..3 -> y0-1..y0+2
    int yo[4];
    #pragma unroll
    for (int l = 0; l < 4; l++) {
        int yy = y0 - 1 + l;
        yy = yy < 0 ? 0 : (yy > 127 ? 127 : yy);
        yo[l] = yy << 7;
    }
    const int to0 = y0 << 7, to1 = (y0 + 1) << 7;

    #define LD4(P) __ldg(((const float4*)(P)) + lane)

    // ring init: a=u(z0-1), b=u(z0), c=u(z0+1)
    float4 a[4], b[4], c[4];
    {
        const int zmi = (z0 > 0 ? z0 - 1 : 0) << 14;
        const int z0i = z0 << 14;
        const int zpi = (z0 + 1) << 14;
        #pragma unroll
        for (int l = 0; l < 4; l++) {
            a[l] = LD4(U + zmi + yo[l]);
            b[l] = LD4(U + z0i + yo[l]);
            c[l] = LD4(U + zpi + yo[l]);
        }
    }
    float4 t0 = LD4(T + (z0 << 14) + to0);
    float4 t1 = LD4(T + (z0 << 14) + to1);

    // 6-wide clamped x-window from a float4
    #define MK6(A, V)                                                  \
        float A[6];                                                    \
        A[1] = V.x; A[2] = V.y; A[3] = V.z; A[4] = V.w;                \
        {   float L_ = __shfl_up_sync(FULL, A[4], 1);                  \
            float R_ = __shfl_down_sync(FULL, A[1], 1);                \
            A[0] = (lane == 0)  ? A[1] : L_;                           \
            A[5] = (lane == 31) ? A[4] : R_; }

    float ain = 0.f, aout = 0.f, ael = 0.f;

    #pragma unroll 2
    for (int zz = 0; zz < 8; zz++) {
        const int z = z0 + zz;

        // prefetch next step's u-planes (z+2, clamped) and t-rows (z+1)
        float4 n[4], tn0, tn1;
        if (zz < 7) {
            int zc = z + 2; zc = zc > 127 ? 127 : zc;
            const int zci = zc << 14;
            #pragma unroll
            for (int l = 0; l < 4; l++) n[l] = LD4(U + zci + yo[l]);
            const int zni = (z + 1) << 14;
            tn0 = LD4(T + zni + to0);
            tn1 = LD4(T + zni + to1);
        }

        // derived z-values for this step
        float4 ez[4];
        #pragma unroll
        for (int l = 0; l < 4; l++) ez[l] = f4sub(c[l], a[l]);
        const float4 sz1 = f4add(c[1], a[1]);
        const float4 sz2 = f4add(c[2], a[2]);

        #pragma unroll
        for (int j = 0; j < 2; j++) {
            const float4 czc = b[j + 1];
            const float4 eyv = f4sub(b[j + 2], b[j]);
            const float4 syv = f4add(b[j + 2], b[j]);
            const float4 gxy = f4sub(ez[j + 2], ez[j]);
            const float4 szv = j ? sz2 : sz1;
            const float4 tt4 = j ? t1 : t0;

            MK6(cc,  czc)
            MK6(ezw, ez[j + 1])
            MK6(eyw, eyv)

            const float syA [4] = { syv.x, syv.y, syv.z, syv.w };
            const float szA [4] = { szv.x, szv.y, szv.z, szv.w };
            const float gxyA[4] = { gxy.x, gxy.y, gxy.z, gxy.w };
            const float ttA [4] = { tt4.x, tt4.y, tt4.z, tt4.w };

            #pragma unroll
            for (int k = 0; k < 4; k++) {
                const float uc = cc[k + 1];
                const float di = ezw[k + 1];
                const float dj = eyw[k + 1];
                const float dk = cc[k + 2] - cc[k];

                const float cii = fmaf(uc, -2.f, szA[k]);
                const float cjj = fmaf(uc, -2.f, syA[k]);
                const float ckk = fmaf(uc, -2.f, cc[k] + cc[k + 2]);
                const float lap = cii + cjj + ckk;

                const float Dik = ezw[k + 2] - ezw[k];
                const float Djk = eyw[k + 2] - eyw[k];
                const float Dij = gxyA[k];

                const float di2 = di * di, dj2 = dj * dj, dk2 = dk * dk;
                const float S = di2 + dj2 + dk2;          // = 4*(ci2+cj2+ck2)

                float acc = di2 * cii;
                acc = fmaf(dj2, cjj, acc);
                acc = fmaf(dk2, ckk, acc);
                acc = fmaf(Dik * Djk, Dij, acc);
                const float curv = fmaf(0.25f, fmaf(S, lap, -acc), lap);

                const float ee = fmaf(0.25f, S, 1e-8f);   // eps + s
                const float oo = fmaf(0.25f, S, 1.f);     // (sqrt(1+s)+eps)^2 ~ 1+s
                const float r_ = rsqrtf(ee * oo * oo);    // sqrt(ee)/oo
                ael = fmaf(curv * curv * ee, r_, ael);

                const float t = ttA[k];
                const float tm1 = t - 1.f;
                ain  = fmaf(uc, tm1 * tm1, ain);
                aout = fmaf(1.f - uc, t * t, aout);
            }
        }

        // advance ring
        if (zz < 7) {
            #pragma unroll
            for (int l = 0; l < 4; l++) { a[l] = b[l]; b[l] = c[l]; c[l] = n[l]; }
            t0 = tn0; t1 = tn1;
        }
    }
    #undef MK6
    #undef LD4

    // ---- block reduction ----
    #pragma unroll
    for (int o = 16; o > 0; o >>= 1) {
        ain  += __shfl_down_sync(FULL, ain,  o);
        aout += __shfl_down_sync(FULL, aout, o);
        ael  += __shfl_down_sync(FULL, ael,  o);
    }
    __shared__ float si[WPB], so[WPB], se[WPB];
    if (lane == 0) { si[wid] = ain; so[wid] = aout; se[wid] = ael; }
    __syncthreads();

    if (threadIdx.x == 0) {
        float A = si[0] + si[1] + si[2] + si[3];
        float B = so[0] + so[1] + so[2] + so[3];
        float E = se[0] + se[1] + se[2] + se[3];
        atomicAdd(&g_acc[0], (double)A);
        atomicAdd(&g_acc[1], (double)B);
        atomicAdd(&g_acc[2], (double)E);
        __threadfence();
        unsigned t = atomicAdd(&g_ticket, 1u);
        if (t == (unsigned)(GRID - 1)) {          // last block finalizes + resets
            __threadfence();
            double s0 = atomicAdd(&g_acc[0], 0.0);
            double s1 = atomicAdd(&g_acc[1], 0.0);
            double s2 = atomicAdd(&g_acc[2], 0.0);
            double res = fabs(s0) + fabs(s1) + s2 + ALPHA * (double)NTOT;
            out[0] = (float)res;
            g_acc[0] = 0.0; g_acc[1] = 0.0; g_acc[2] = 0.0;
            g_ticket = 0u;
        }
    }
}

extern "C" void kernel_launch(void* const* d_in, const int* in_sizes, int n_in,
                              void* d_out, int out_size) {
    const float* y_pred = (const float*)d_in[0];
    const float* y_true = (const float*)d_in[1];
    ace_main<<<GRID, BLOCK>>>(y_pred, y_true, (float*)d_out);
}